// round 16
// baseline (speedup 1.0000x reference)
#include <cuda_runtime.h>
#include <math.h>

#define NT 256
#define RPB 8
#define NBLK 128
#define KC 32
#define KCBYTES (KC * 512 * 4)
#define P0 164
#define P1 260

typedef unsigned long long ull;

// ---------------- device scratch ----------------
// Weight layout: per 32-k chunk, k-pairs: buf[kp*1024 + c*2 + j] = w_{k=kp*2+j}[c],
// where c = 4*u + gate (interleaved i,f,g,o).
__device__ float g_W0ext[160 * 512];   // layer0 k: 0..7 x, 8..23 emb, 24..31 ZERO, 32..159 W_hh0
__device__ float g_W1cat[256 * 512];   // layer1 k: 0..127 W_ih1, 128..255 W_hh1
__device__ float g_b0[512];            // interleaved
__device__ float g_b1[512];
__device__ float g_W1T[184 * 128];     // [k][u]  (diffusion)
__device__ float g_W2s[128 * 128];     // [u][v] = W2[v][u]
__device__ float g_A1t[100 * 128];
__device__ float g_cy[100];
__device__ float g_ce[100];

// ---------------- prologue ----------------
__global__ void prologue_kernel(const float* __restrict__ W_ih0, const float* __restrict__ W_hh0,
                                const float* __restrict__ b_ih0, const float* __restrict__ b_hh0,
                                const float* __restrict__ W_ih1, const float* __restrict__ W_hh1,
                                const float* __restrict__ b_ih1, const float* __restrict__ b_hh1,
                                const float* __restrict__ W1,    const float* __restrict__ W2) {
    int tid = blockIdx.x * blockDim.x + threadIdx.x;
    int nth = gridDim.x * blockDim.x;

    for (int i = tid; i < 160 * 512; i += nth) {
        int chunk = i / 16384;
        int rem = i & 16383;
        int kp = rem >> 10, q = rem & 1023;
        int c = q >> 1, j = q & 1;
        int k = chunk * 32 + kp * 2 + j;
        int u = c >> 2, gi = c & 3;
        int row = gi * 128 + u;
        float v;
        if (k < 24)      v = W_ih0[row * 24 + k];
        else if (k < 32) v = 0.0f;
        else             v = W_hh0[row * 128 + (k - 32)];
        g_W0ext[i] = v;
    }
    for (int i = tid; i < 256 * 512; i += nth) {
        int chunk = i / 16384;
        int rem = i & 16383;
        int kp = rem >> 10, q = rem & 1023;
        int c = q >> 1, j = q & 1;
        int k = chunk * 32 + kp * 2 + j;
        int u = c >> 2, gi = c & 3;
        int row = gi * 128 + u;
        g_W1cat[i] = (k < 128) ? W_ih1[row * 128 + k] : W_hh1[row * 128 + (k - 128)];
    }
    for (int i = tid; i < 512; i += nth) {
        int u = i >> 2, gi = i & 3;
        int row = gi * 128 + u;
        g_b0[i] = b_ih0[row] + b_hh0[row];
        g_b1[i] = b_ih1[row] + b_hh1[row];
    }
    for (int i = tid; i < 184 * 128; i += nth) {
        int k = i >> 7, u = i & 127;
        g_W1T[i] = W1[u * 184 + k];
    }
    for (int i = tid; i < 128 * 128; i += nth) {
        int u = i >> 7, v = i & 127;
        g_W2s[i] = W2[v * 128 + u];
    }
    for (int i = tid; i < 100 * 128; i += nth) {
        int t = i >> 7, u = i & 127;
        float acc = 0.f;
        #pragma unroll
        for (int j = 0; j < 8; j++) {
            float f = expf(-logf(10000.0f) * (float)j / 8.0f);
            float a = (float)t * f;
            acc += W1[u * 184 + 152 + j] * cosf(a);
            acc += W1[u * 184 + 160 + j] * sinf(a);
        }
        g_A1t[i] = acc;
    }
    if (tid == 0) {
        float ab = 1.0f;
        for (int t = 0; t < 100; t++) {
            float beta  = 1e-4f + (0.02f - 1e-4f) * (float)t / 99.0f;
            float alpha = 1.0f - beta;
            ab *= alpha;
            if (t == 0) {
                float p = sqrtf(ab) + 1e-8f;
                g_cy[0] = 1.0f / p;
                g_ce[0] = sqrtf(1.0f - ab) / p;
            } else {
                float inv = 1.0f / (sqrtf(alpha) + 1e-8f);
                g_cy[t] = inv;
                g_ce[t] = beta / (sqrtf(1.0f - ab) + 1e-8f) * inv;
            }
        }
    }
}

// ---------------- fast math helpers ----------------
__device__ __forceinline__ float sigf(float x) {
    float xc = fminf(fmaxf(x, -30.f), 30.f);
    return __fdividef(1.0f, 1.0f + __expf(-xc));
}
__device__ __forceinline__ float tanhf_fast(float x) {
    float xc = fminf(fmaxf(x, -15.f), 15.f);
    float e = __expf(2.0f * xc);
    return __fdividef(e - 1.0f, e + 1.0f);
}
__device__ __forceinline__ void ffma2(ull &d, ull a, ull b) {
    asm("fma.rn.f32x2 %0, %1, %2, %0;" : "+l"(d) : "l"(a), "l"(b));
}
__device__ __forceinline__ ull dup2(float x) {
    ull r;
    asm("mov.b64 %0, {%1, %1};" : "=l"(r) : "f"(x));
    return r;
}
__device__ __forceinline__ ull pack2(float lo, float hi) {
    ull r;
    asm("mov.b64 %0, {%1, %2};" : "=l"(r) : "f"(lo), "f"(hi));
    return r;
}
__device__ __forceinline__ float2 unpack2(ull v) {
    float2 r;
    asm("mov.b64 {%0, %1}, %2;" : "=f"(r.x), "=f"(r.y) : "l"(v));
    return r;
}
__device__ __forceinline__ float foldadd(ull v) {
    float2 p = unpack2(v);
    return p.x + p.y;
}
__device__ __forceinline__ unsigned smem_u32(const void* p) {
    unsigned a;
    asm("{ .reg .u64 t; cvta.to.shared.u64 t, %1; cvt.u32.u64 %0, t; }" : "=r"(a) : "l"(p));
    return a;
}

// ---------------- bulk staging (TMA path) ----------------
__device__ __forceinline__ void bulk_stage(unsigned dst, const float* __restrict__ src,
                                           unsigned bytes, unsigned mbar) {
    asm volatile("mbarrier.arrive.expect_tx.shared.b64 _, [%0], %1;"
                 :: "r"(mbar), "r"(bytes) : "memory");
    asm volatile("cp.async.bulk.shared::cluster.global.mbarrier::complete_tx::bytes [%0], [%1], %2, [%3];"
                 :: "r"(dst), "l"(src), "r"(bytes), "r"(mbar) : "memory");
}
__device__ __forceinline__ void mbar_wait(unsigned mbar, int phase) {
    asm volatile(
        "{\n\t.reg .pred P1;\n\t"
        "WAIT_LOOP_%=:\n\t"
        "mbarrier.try_wait.parity.shared.b64 P1, [%0], %1;\n\t"
        "@P1 bra.uni WAIT_DONE_%=;\n\t"
        "bra.uni WAIT_LOOP_%=;\n\t"
        "WAIT_DONE_%=:\n\t}"
        :: "r"(mbar), "r"(phase) : "memory");
}

// ---------------- smem layout (floats) ----------------
#define SM_XA     0        // [8][164]: k 0..7 x_t, 8..23 emb, 24..31 zero, 32..159 h0
#define SM_XB     1312
#define SM_X1A    2624     // [8][260]: k 0..127 h0new, 128..255 h1
#define SM_X1B    4704
#define SM_STAGE  6784     // 2 x (KC*512) = 32768 (byte 27136, 16B aligned)
#define SM_B0     39552    // 512
#define SM_B1     40064    // 512
#define SM_EMBR   40576    // 128
#define SM_EMBT   40704    // 128
#define SM_ENC    40832    // [128 u][8 r] = 1024
#define SM_MH1    41856    // 1024
#define SM_W1Y    42880    // 128
#define SM_W3     43008    // 128
#define SM_BM2    43136    // 128
#define SM_XFT    43264    // 48
#define SM_HES    43312    // 32
#define SM_CY     43344    // 100
#define SM_CE     43444    // 100
#define SM_RED    43544    // 32
#define SM_A1     43576    // 12800
#define SM_MB     56376    // 2 mbarriers (8B aligned)
#define SM_TOTAL  56380
#define SMEM_BYTES (SM_TOTAL * 4)

__device__ __forceinline__ void barh(int half) {
    asm volatile("bar.sync %0, 128;" :: "r"(half + 1) : "memory");
}

// ---------------- main fused kernel ----------------
__global__ __launch_bounds__(NT, 1)
void fused_kernel(const float* __restrict__ x_hist, const float* __restrict__ x_future,
                  const float* __restrict__ y0, const int* __restrict__ turb_idx,
                  const float* __restrict__ init_noise, const float* __restrict__ turb_emb,
                  const float* __restrict__ b1m, const float* __restrict__ b2m,
                  const float* __restrict__ W3, const float* __restrict__ b3p,
                  float* __restrict__ out) {
    extern __shared__ float sm[];
    float* xA    = sm + SM_XA;
    float* xB    = sm + SM_XB;
    float* x1A   = sm + SM_X1A;
    float* x1B   = sm + SM_X1B;
    float* stg   = sm + SM_STAGE;
    float* b0s   = sm + SM_B0;
    float* b1s   = sm + SM_B1;
    float* embr  = sm + SM_EMBR;
    float* embT  = sm + SM_EMBT;
    float* encT  = sm + SM_ENC;
    float* mh1   = sm + SM_MH1;
    float* w1ys  = sm + SM_W1Y;
    float* w3s   = sm + SM_W3;
    float* bm2s  = sm + SM_BM2;
    float* xfT   = sm + SM_XFT;
    float* hes   = sm + SM_HES;
    float* cys   = sm + SM_CY;
    float* ces   = sm + SM_CE;
    float* red   = sm + SM_RED;
    float* a1s   = sm + SM_A1;

    const int tid  = threadIdx.x;
    const int brow = blockIdx.x * RPB;

    const unsigned stg_u32 = smem_u32(stg);
    const unsigned mb0 = smem_u32(sm + SM_MB);
    const unsigned mb1 = mb0 + 8;

    // ---- init ----
    for (int i = tid; i < 6784; i += NT) sm[i] = 0.0f;   // xA,xB,x1A,x1B
    for (int i = tid; i < 512; i += NT) { b0s[i] = g_b0[i]; b1s[i] = g_b1[i]; }
    for (int i = tid; i < 12800; i += NT) a1s[i] = g_A1t[i];
    if (tid < 128) {
        int r = tid >> 4, k = tid & 15;
        embr[r * 16 + k] = turb_emb[turb_idx[brow + r] * 16 + k];
    }
    if (tid < 128) {
        w1ys[tid] = g_W1T[151 * 128 + tid];
        w3s[tid]  = W3[tid];
        bm2s[tid] = b2m[tid];
    }
    if (tid < 100) { cys[tid] = g_cy[tid]; ces[tid] = g_ce[tid]; }
    if (tid == 0) {
        asm volatile("mbarrier.init.shared.b64 [%0], 1;" :: "r"(mb0) : "memory");
        asm volatile("mbarrier.init.shared.b64 [%0], 1;" :: "r"(mb1) : "memory");
    }
    __syncthreads();
    if (tid < 128) {
        int k = tid >> 3, r = tid & 7;
        float v = embr[r * 16 + k];
        embT[k * 8 + r] = v;
        xA[r * P0 + 8 + k] = v;
        xB[r * P0 + 8 + k] = v;
    }
    const int xk = tid & 7, xr = (tid >> 3) & 7;
    if (tid < 64) xA[xr * P0 + xk] = __ldg(&x_hist[((brow + xr) * 96 + 0) * 8 + xk]);
    __syncthreads();

    const int u   = tid >> 1;        // unit 0..127
    const int g0  = u << 2;          // interleaved cols (i,f,g,o)
    const int u8  = u << 3;          // weight pair offset within a k-pair block
    const int r0g = (tid & 1) << 2;  // rows r0g..r0g+3

    const float4 b0v = *reinterpret_cast<const float4*>(b0s + g0);
    const float4 b1v = *reinterpret_cast<const float4*>(b1s + g0);

    float c0r[4] = {0.f, 0.f, 0.f, 0.f};
    float c1r[4] = {0.f, 0.f, 0.f, 0.f};

    float* xcur = xA;  float* xnxt = xB;
    float* x1cur = x1A; float* x1nxt = x1B;
    int par = 0, phase0 = 0, phase1 = 0;

    float xnext = 0.f;
    if (tid < 64) xnext = __ldg(&x_hist[((brow + xr) * 96 + 1) * 8 + xk]);

    if (tid == 0) bulk_stage(stg_u32, g_W0ext, KCBYTES, mb0);

    // =================== LSTM encoder: 96 steps x 13 chunks ===================
    for (int t = 0; t < 96; t++) {
        ull a00=0,a01=0,a02=0,a03=0, a10=0,a11=0,a12=0,a13=0;
        ull a20=0,a21=0,a22=0,a23=0, a30=0,a31=0,a32=0,a33=0;

        #pragma unroll 1
        for (int cc = 0; cc < 13; cc++) {
            if (par == 0) { mbar_wait(mb0, phase0); phase0 ^= 1; }
            else          { mbar_wait(mb1, phase1); phase1 ^= 1; }
            __syncthreads();

            if (tid == 0 && !(t == 95 && cc == 12)) {
                int nc = (cc + 1 == 13) ? 0 : cc + 1;
                const float* src = (nc < 5) ? (g_W0ext + nc * KC * 512)
                                            : (g_W1cat + (nc - 5) * KC * 512);
                bulk_stage(stg_u32 + (unsigned)(par ^ 1) * KCBYTES, src, KCBYTES,
                           (par == 0) ? mb1 : mb0);
            }

            const float* buf = stg + par * (KC * 512);
            const float* xb;
            int pitch;
            if (cc < 5) { xb = xcur + cc * KC;        pitch = P0; }
            else        { xb = x1cur + (cc - 5) * KC; pitch = P1; }
            const float* x0p = xb + (r0g    ) * pitch;
            const float* x1p = xb + (r0g + 1) * pitch;
            const float* x2p = xb + (r0g + 2) * pitch;
            const float* x3p = xb + (r0g + 3) * pitch;

            #pragma unroll 8
            for (int kk4 = 0; kk4 < 8; kk4++) {
                const ulonglong2 wA = *reinterpret_cast<const ulonglong2*>(buf + (kk4 * 2    ) * 1024 + u8);
                const ulonglong2 wA2= *reinterpret_cast<const ulonglong2*>(buf + (kk4 * 2    ) * 1024 + u8 + 4);
                const ulonglong2 wB = *reinterpret_cast<const ulonglong2*>(buf + (kk4 * 2 + 1) * 1024 + u8);
                const ulonglong2 wB2= *reinterpret_cast<const ulonglong2*>(buf + (kk4 * 2 + 1) * 1024 + u8 + 4);
                const ulonglong2 x0 = *reinterpret_cast<const ulonglong2*>(x0p + kk4 * 4);
                const ulonglong2 x1 = *reinterpret_cast<const ulonglong2*>(x1p + kk4 * 4);
                const ulonglong2 x2 = *reinterpret_cast<const ulonglong2*>(x2p + kk4 * 4);
                const ulonglong2 x3 = *reinterpret_cast<const ulonglong2*>(x3p + kk4 * 4);
                // k-pair 0 (k0,k1): gate pairs wA.x=g0, wA.y=g1, wA2.x=g2, wA2.y=g3
                ffma2(a00, wA.x,  x0.x); ffma2(a10, wA.y,  x0.x); ffma2(a20, wA2.x, x0.x); ffma2(a30, wA2.y, x0.x);
                ffma2(a01, wA.x,  x1.x); ffma2(a11, wA.y,  x1.x); ffma2(a21, wA2.x, x1.x); ffma2(a31, wA2.y, x1.x);
                ffma2(a02, wA.x,  x2.x); ffma2(a12, wA.y,  x2.x); ffma2(a22, wA2.x, x2.x); ffma2(a32, wA2.y, x2.x);
                ffma2(a03, wA.x,  x3.x); ffma2(a13, wA.y,  x3.x); ffma2(a23, wA2.x, x3.x); ffma2(a33, wA2.y, x3.x);
                // k-pair 1 (k2,k3)
                ffma2(a00, wB.x,  x0.y); ffma2(a10, wB.y,  x0.y); ffma2(a20, wB2.x, x0.y); ffma2(a30, wB2.y, x0.y);
                ffma2(a01, wB.x,  x1.y); ffma2(a11, wB.y,  x1.y); ffma2(a21, wB2.x, x1.y); ffma2(a31, wB2.y, x1.y);
                ffma2(a02, wB.x,  x2.y); ffma2(a12, wB.y,  x2.y); ffma2(a22, wB2.x, x2.y); ffma2(a32, wB2.y, x2.y);
                ffma2(a03, wB.x,  x3.y); ffma2(a13, wB.y,  x3.y); ffma2(a23, wB2.x, x3.y); ffma2(a33, wB2.y, x3.y);
            }
            par ^= 1;

            if (cc == 4) {
                // combine layer 0 -> h0new into x1cur[.][0..127] and xnxt[.][32..159]
                #pragma unroll
                for (int ri = 0; ri < 4; ri++) {
                    float gi, gf, gg, go;
                    if (ri == 0) { gi = foldadd(a00); gf = foldadd(a10); gg = foldadd(a20); go = foldadd(a30); }
                    else if (ri == 1) { gi = foldadd(a01); gf = foldadd(a11); gg = foldadd(a21); go = foldadd(a31); }
                    else if (ri == 2) { gi = foldadd(a02); gf = foldadd(a12); gg = foldadd(a22); go = foldadd(a32); }
                    else { gi = foldadd(a03); gf = foldadd(a13); gg = foldadd(a23); go = foldadd(a33); }
                    gi += b0v.x; gf += b0v.y; gg += b0v.z; go += b0v.w;
                    float cv = sigf(gf) * c0r[ri] + sigf(gi) * tanhf_fast(gg);
                    c0r[ri] = cv;
                    float h = sigf(go) * tanhf_fast(cv);
                    int row = r0g + ri;
                    x1cur[row * P1 + u] = h;
                    xnxt[row * P0 + 32 + u] = h;
                }
                a00=a01=a02=a03=a10=a11=a12=a13=0ULL;
                a20=a21=a22=a23=a30=a31=a32=a33=0ULL;
                if (tid < 64) {
                    if (t < 95) xnxt[xr * P0 + xk] = xnext;
                    if (t + 2 < 96) xnext = __ldg(&x_hist[((brow + xr) * 96 + (t + 2)) * 8 + xk]);
                }
            } else if (cc == 12) {
                // combine layer 1 -> h1new into x1nxt[.][128..255]
                #pragma unroll
                for (int ri = 0; ri < 4; ri++) {
                    float gi, gf, gg, go;
                    if (ri == 0) { gi = foldadd(a00); gf = foldadd(a10); gg = foldadd(a20); go = foldadd(a30); }
                    else if (ri == 1) { gi = foldadd(a01); gf = foldadd(a11); gg = foldadd(a21); go = foldadd(a31); }
                    else if (ri == 2) { gi = foldadd(a02); gf = foldadd(a12); gg = foldadd(a22); go = foldadd(a32); }
                    else { gi = foldadd(a03); gf = foldadd(a13); gg = foldadd(a23); go = foldadd(a33); }
                    gi += b1v.x; gf += b1v.y; gg += b1v.z; go += b1v.w;
                    float cv = sigf(gf) * c1r[ri] + sigf(gi) * tanhf_fast(gg);
                    c1r[ri] = cv;
                    float h = sigf(go) * tanhf_fast(cv);
                    x1nxt[(r0g + ri) * P1 + 128 + u] = h;
                }
            }
        }

        { float* tmp = xcur; xcur = xnxt; xnxt = tmp; }
        { float* tmp = x1cur; x1cur = x1nxt; x1nxt = tmp; }
    }
    __syncthreads();
    // transpose final h1 -> encT[u][r]
    for (int i = tid; i < 1024; i += NT) {
        int uo = i >> 3, r = i & 7;
        encT[i] = x1cur[r * P1 + 128 + uo];
    }
    __syncthreads();

    // =================== AR + diffusion (R12-proven, two halves) ===================
    const int half = tid >> 7;
    const int local = tid & 127;
    const int uu = tid & 127;
    const int r0d = half * 4;
    const float b3v = __ldg(&b3p[0]);

    float w2r[128];
    #pragma unroll
    for (int uw = 0; uw < 128; uw++) w2r[uw] = __ldg(&g_W2s[(uw << 7) + uu]);

    const float w1yv = w1ys[uu];
    const float w3v  = w3s[uu];
    const float bm2v = bm2s[uu];
    const ull bm2p = pack2(bm2v, bm2v);

    float ypa[4];
    #pragma unroll
    for (int j = 0; j < 4; j++) ypa[j] = __ldg(&y0[brow + r0d + j]);

    const int wih = (tid >> 5) & 3;
    const int lane = tid & 31;

    for (int p = 0; p < 8; p++) {
        if (local < 24) {
            int k = local >> 2, rl = local & 3;
            xfT[half * 24 + k * 4 + rl] = __ldg(&x_future[(brow + r0d + rl) * 48 + p * 6 + k]);
        }
        if (local < 16) {
            int j = local & 7;
            float f = __expf(-logf(10000.0f) * (float)j / 8.0f);
            float a = (float)p * f;
            hes[half * 16 + local] = (local < 8) ? cosf(a) : sinf(a);
        }
        float yra[4];
        #pragma unroll
        for (int j = 0; j < 4; j++) yra[j] = __ldg(&init_noise[p * 1024 + brow + r0d + j]);
        barh(half);

        float4 base = make_float4(0.f, 0.f, 0.f, 0.f);
        {
            #pragma unroll 8
            for (int k = 0; k < 128; k++) {
                float w = __ldg(&g_W1T[(k << 7) + uu]);
                const float4 h = *reinterpret_cast<const float4*>(&encT[k * 8 + r0d]);
                base.x += w * h.x; base.y += w * h.y; base.z += w * h.z; base.w += w * h.w;
            }
            #pragma unroll
            for (int k = 0; k < 6; k++) {
                float w = __ldg(&g_W1T[((128 + k) << 7) + uu]);
                const float4 x = *reinterpret_cast<const float4*>(&xfT[half * 24 + k * 4]);
                base.x += w * x.x; base.y += w * x.y; base.z += w * x.z; base.w += w * x.w;
            }
            #pragma unroll
            for (int k = 0; k < 16; k++) {
                float w = __ldg(&g_W1T[((134 + k) << 7) + uu]);
                const float* ep = &embT[k * 8 + r0d];
                base.x += w * ep[0]; base.y += w * ep[1]; base.z += w * ep[2]; base.w += w * ep[3];
            }
            {
                float w = __ldg(&g_W1T[(150 << 7) + uu]);
                base.x += w * ypa[0]; base.y += w * ypa[1]; base.z += w * ypa[2]; base.w += w * ypa[3];
            }
            float hsum = 0.f;
            #pragma unroll
            for (int k = 0; k < 16; k++) hsum += __ldg(&g_W1T[((168 + k) << 7) + uu]) * hes[half * 16 + k];
            float bb = __ldg(&b1m[uu]) + hsum;
            base.x += bb; base.y += bb; base.z += bb; base.w += bb;
        }

        for (int tt = 99; tt >= 0; tt--) {
            {
                float av = a1s[tt * 128 + uu];
                float4 m;
                m.x = fmaxf(base.x + yra[0] * w1yv + av, 0.f);
                m.y = fmaxf(base.y + yra[1] * w1yv + av, 0.f);
                m.z = fmaxf(base.z + yra[2] * w1yv + av, 0.f);
                m.w = fmaxf(base.w + yra[3] * w1yv + av, 0.f);
                *reinterpret_cast<float4*>(&mh1[(uu << 3) + r0d]) = m;
            }
            barh(half);

            {
                ull acc01 = bm2p;
                ull acc23 = bm2p;
                #pragma unroll
                for (int uw = 0; uw < 128; uw++) {
                    const ulonglong2 h = *reinterpret_cast<const ulonglong2*>(&mh1[(uw << 3) + r0d]);
                    ull dw = dup2(w2r[uw]);
                    ffma2(acc01, dw, h.x);
                    ffma2(acc23, dw, h.y);
                }
                float2 a01 = unpack2(acc01);
                float2 a23 = unpack2(acc23);
                float e0 = fmaxf(a01.x, 0.f) * w3v;
                float e1 = fmaxf(a01.y, 0.f) * w3v;
                float e2 = fmaxf(a23.x, 0.f) * w3v;
                float e3 = fmaxf(a23.y, 0.f) * w3v;
                #pragma unroll
                for (int off = 16; off > 0; off >>= 1) {
                    e0 += __shfl_down_sync(0xffffffffu, e0, off);
                    e1 += __shfl_down_sync(0xffffffffu, e1, off);
                    e2 += __shfl_down_sync(0xffffffffu, e2, off);
                    e3 += __shfl_down_sync(0xffffffffu, e3, off);
                }
                if (lane == 0)
                    *reinterpret_cast<float4*>(&red[half * 16 + wih * 4]) = make_float4(e0, e1, e2, e3);
            }
            barh(half);

            {
                const float4 q0 = *reinterpret_cast<const float4*>(&red[half * 16 + 0]);
                const float4 q1 = *reinterpret_cast<const float4*>(&red[half * 16 + 4]);
                const float4 q2 = *reinterpret_cast<const float4*>(&red[half * 16 + 8]);
                const float4 q3 = *reinterpret_cast<const float4*>(&red[half * 16 + 12]);
                float cy = cys[tt], ce = ces[tt];
                yra[0] = cy * yra[0] - ce * (b3v + q0.x + q1.x + q2.x + q3.x);
                yra[1] = cy * yra[1] - ce * (b3v + q0.y + q1.y + q2.y + q3.y);
                yra[2] = cy * yra[2] - ce * (b3v + q0.z + q1.z + q2.z + q3.z);
                yra[3] = cy * yra[3] - ce * (b3v + q0.w + q1.w + q2.w + q3.w);
            }
        }

        if (local < 4) {
            float v = (local == 0) ? yra[0] : (local == 1) ? yra[1] : (local == 2) ? yra[2] : yra[3];
            out[(brow + r0d + local) * 8 + p] = v;
        }
        #pragma unroll
        for (int j = 0; j < 4; j++) ypa[j] = yra[j];
    }
}

// ---------------- launch ----------------
extern "C" void kernel_launch(void* const* d_in, const int* in_sizes, int n_in,
                              void* d_out, int out_size) {
    const float* x_hist     = (const float*)d_in[0];
    const float* x_future   = (const float*)d_in[1];
    const float* y0         = (const float*)d_in[2];
    const int*   turb_idx   = (const int*)d_in[3];
    const float* init_noise = (const float*)d_in[5];
    const float* turb_emb   = (const float*)d_in[6];
    const float* W_ih0      = (const float*)d_in[7];
    const float* W_hh0      = (const float*)d_in[8];
    const float* b_ih0      = (const float*)d_in[9];
    const float* b_hh0      = (const float*)d_in[10];
    const float* W_ih1      = (const float*)d_in[11];
    const float* W_hh1      = (const float*)d_in[12];
    const float* b_ih1      = (const float*)d_in[13];
    const float* b_hh1      = (const float*)d_in[14];
    const float* W1         = (const float*)d_in[15];
    const float* b1m        = (const float*)d_in[16];
    const float* W2         = (const float*)d_in[17];
    const float* b2m        = (const float*)d_in[18];
    const float* W3         = (const float*)d_in[19];
    const float* b3         = (const float*)d_in[20];
    float* out = (float*)d_out;

    prologue_kernel<<<128, 256>>>(W_ih0, W_hh0, b_ih0, b_hh0,
                                  W_ih1, W_hh1, b_ih1, b_hh1, W1, W2);

    cudaFuncSetAttribute(fused_kernel, cudaFuncAttributeMaxDynamicSharedMemorySize, SMEM_BYTES);
    fused_kernel<<<NBLK, NT, SMEM_BYTES>>>(x_hist, x_future, y0, turb_idx, init_noise,
                                           turb_emb, b1m, b2m, W3, b3, out);
}

// round 17
// speedup vs baseline: 1.0382x; 1.0382x over previous
#include <cuda_runtime.h>
#include <math.h>

#define NT 256
#define RPB 8
#define NBLK 128
#define KC 16
#define KCF (KC * 512)
#define KCBYTES (KCF * 4)

typedef unsigned long long ull;

// ---------------- device scratch ----------------
// Interleaved gate layout: column c = 4*u + gate, gate in {i,f,g,o}
__device__ float g_W0ext[160 * 512];   // layer0 k: 0..23 W_ih0, 24..31 ZERO, 32..159 W_hh0
__device__ float g_W1cat[256 * 512];   // layer1 k: 0..127 W_ih1, 128..255 W_hh1
__device__ float g_b0[512];
__device__ float g_b1[512];
__device__ float g_W1T[184 * 128];     // [k][u]  (diffusion)
__device__ float g_W2s[128 * 128];     // [u][v] = W2[v][u]
__device__ float g_A1t[100 * 128];
__device__ float g_cy[100];
__device__ float g_ce[100];

// ---------------- prologue ----------------
__global__ void prologue_kernel(const float* __restrict__ W_ih0, const float* __restrict__ W_hh0,
                                const float* __restrict__ b_ih0, const float* __restrict__ b_hh0,
                                const float* __restrict__ W_ih1, const float* __restrict__ W_hh1,
                                const float* __restrict__ b_ih1, const float* __restrict__ b_hh1,
                                const float* __restrict__ W1,    const float* __restrict__ W2) {
    int tid = blockIdx.x * blockDim.x + threadIdx.x;
    int nth = gridDim.x * blockDim.x;

    for (int i = tid; i < 160 * 512; i += nth) {
        int k = i >> 9, c = i & 511;
        int u = c >> 2, gi = c & 3;
        int row = gi * 128 + u;
        float v;
        if (k < 24)      v = W_ih0[row * 24 + k];
        else if (k < 32) v = 0.0f;
        else             v = W_hh0[row * 128 + (k - 32)];
        g_W0ext[i] = v;
    }
    for (int i = tid; i < 256 * 512; i += nth) {
        int k = i >> 9, c = i & 511;
        int u = c >> 2, gi = c & 3;
        int row = gi * 128 + u;
        g_W1cat[i] = (k < 128) ? W_ih1[row * 128 + k] : W_hh1[row * 128 + (k - 128)];
    }
    for (int i = tid; i < 512; i += nth) {
        int u = i >> 2, gi = i & 3;
        int row = gi * 128 + u;
        g_b0[i] = b_ih0[row] + b_hh0[row];
        g_b1[i] = b_ih1[row] + b_hh1[row];
    }
    for (int i = tid; i < 184 * 128; i += nth) {
        int k = i >> 7, u = i & 127;
        g_W1T[i] = W1[u * 184 + k];
    }
    for (int i = tid; i < 128 * 128; i += nth) {
        int u = i >> 7, v = i & 127;
        g_W2s[i] = W2[v * 128 + u];
    }
    for (int i = tid; i < 100 * 128; i += nth) {
        int t = i >> 7, u = i & 127;
        float acc = 0.f;
        #pragma unroll
        for (int j = 0; j < 8; j++) {
            float f = expf(-logf(10000.0f) * (float)j / 8.0f);
            float a = (float)t * f;
            acc += W1[u * 184 + 152 + j] * cosf(a);
            acc += W1[u * 184 + 160 + j] * sinf(a);
        }
        g_A1t[i] = acc;
    }
    if (tid == 0) {
        float ab = 1.0f;
        for (int t = 0; t < 100; t++) {
            float beta  = 1e-4f + (0.02f - 1e-4f) * (float)t / 99.0f;
            float alpha = 1.0f - beta;
            ab *= alpha;
            if (t == 0) {
                float p = sqrtf(ab) + 1e-8f;
                g_cy[0] = 1.0f / p;
                g_ce[0] = sqrtf(1.0f - ab) / p;
            } else {
                float inv = 1.0f / (sqrtf(alpha) + 1e-8f);
                g_cy[t] = inv;
                g_ce[t] = beta / (sqrtf(1.0f - ab) + 1e-8f) * inv;
            }
        }
    }
}

// ---------------- fast math helpers ----------------
__device__ __forceinline__ float sigf(float x) {
    float xc = fminf(fmaxf(x, -30.f), 30.f);
    return __fdividef(1.0f, 1.0f + __expf(-xc));
}
__device__ __forceinline__ float tanhf_fast(float x) {
    float xc = fminf(fmaxf(x, -15.f), 15.f);
    float e = __expf(2.0f * xc);
    return __fdividef(e - 1.0f, e + 1.0f);
}
__device__ __forceinline__ void ffma2(ull &d, ull a, ull b) {
    asm("fma.rn.f32x2 %0, %1, %2, %0;" : "+l"(d) : "l"(a), "l"(b));
}
__device__ __forceinline__ ull dup2(float x) {
    ull r;
    asm("mov.b64 %0, {%1, %1};" : "=l"(r) : "f"(x));
    return r;
}
__device__ __forceinline__ ull pack2(float lo, float hi) {
    ull r;
    asm("mov.b64 %0, {%1, %2};" : "=l"(r) : "f"(lo), "f"(hi));
    return r;
}
__device__ __forceinline__ float2 unpack2(ull v) {
    float2 r;
    asm("mov.b64 {%0, %1}, %2;" : "=f"(r.x), "=f"(r.y) : "l"(v));
    return r;
}
__device__ __forceinline__ unsigned smem_u32(const void* p) {
    unsigned a;
    asm("{ .reg .u64 t; cvta.to.shared.u64 t, %1; cvt.u32.u64 %0, t; }" : "=r"(a) : "l"(p));
    return a;
}

// ---------------- bulk staging (TMA path) ----------------
__device__ __forceinline__ void bulk_stage(unsigned dst, const float* __restrict__ src,
                                           unsigned bytes, unsigned mbar) {
    asm volatile("mbarrier.arrive.expect_tx.shared.b64 _, [%0], %1;"
                 :: "r"(mbar), "r"(bytes) : "memory");
    asm volatile("cp.async.bulk.shared::cluster.global.mbarrier::complete_tx::bytes [%0], [%1], %2, [%3];"
                 :: "r"(dst), "l"(src), "r"(bytes), "r"(mbar) : "memory");
}
__device__ __forceinline__ void mbar_wait(unsigned mbar, int phase) {
    asm volatile(
        "{\n\t.reg .pred P1;\n\t"
        "WAIT_LOOP_%=:\n\t"
        "mbarrier.try_wait.parity.shared.b64 P1, [%0], %1;\n\t"
        "@P1 bra.uni WAIT_DONE_%=;\n\t"
        "bra.uni WAIT_LOOP_%=;\n\t"
        "WAIT_DONE_%=:\n\t}"
        :: "r"(mbar), "r"(phase) : "memory");
}

// ---------------- smem layout (floats) ----------------
#define SM_XFIX   0        // [32][8]: rows 0..7 x_t, 8..23 emb, 24..31 zero
#define SM_H0A    256      // [128][8]
#define SM_H0B    1280
#define SM_H1A    2304
#define SM_H1B    3328
#define SM_STAGE  4352     // 4 x (KC*512) = 32768 (byte 17408, 16B aligned)
#define SM_B0     37120
#define SM_B1     37632
#define SM_EMBR   38144
#define SM_EMBT   38272
#define SM_MH1    38400
#define SM_W1Y    39424
#define SM_W3     39552
#define SM_BM2    39680
#define SM_XFT    39808
#define SM_HES    39856
#define SM_CY     39888
#define SM_CE     39988
#define SM_RED    40088
#define SM_A1     40120    // 12800
#define SM_MB     52920    // 4 mbarriers (32B, 8B aligned)
#define SM_TOTAL  52928
#define SMEM_BYTES (SM_TOTAL * 4)

__device__ __forceinline__ void barh(int half) {
    asm volatile("bar.sync %0, 128;" :: "r"(half + 1) : "memory");
}

// ---------------- main fused kernel ----------------
__global__ __launch_bounds__(NT, 1)
void fused_kernel(const float* __restrict__ x_hist, const float* __restrict__ x_future,
                  const float* __restrict__ y0, const int* __restrict__ turb_idx,
                  const float* __restrict__ init_noise, const float* __restrict__ turb_emb,
                  const float* __restrict__ b1m, const float* __restrict__ b2m,
                  const float* __restrict__ W3, const float* __restrict__ b3p,
                  float* __restrict__ out) {
    extern __shared__ float sm[];
    float* xfix  = sm + SM_XFIX;
    float* h0A   = sm + SM_H0A;
    float* h0B   = sm + SM_H0B;
    float* h1A   = sm + SM_H1A;
    float* h1B   = sm + SM_H1B;
    float* stg   = sm + SM_STAGE;
    float* b0s   = sm + SM_B0;
    float* b1s   = sm + SM_B1;
    float* embr  = sm + SM_EMBR;
    float* embT  = sm + SM_EMBT;
    float* mh1   = sm + SM_MH1;
    float* w1ys  = sm + SM_W1Y;
    float* w3s   = sm + SM_W3;
    float* bm2s  = sm + SM_BM2;
    float* xfT   = sm + SM_XFT;
    float* hes   = sm + SM_HES;
    float* cys   = sm + SM_CY;
    float* ces   = sm + SM_CE;
    float* red   = sm + SM_RED;
    float* a1s   = sm + SM_A1;

    const int tid  = threadIdx.x;
    const int brow = blockIdx.x * RPB;

    const unsigned stg_u32 = smem_u32(stg);
    const unsigned mbb = smem_u32(sm + SM_MB);

    // ---- init ----
    for (int i = tid; i < 256; i += NT) xfix[i] = 0.0f;
    for (int i = tid; i < 4096; i += NT) h0A[i] = 0.0f;   // h0A,h0B,h1A,h1B
    for (int i = tid; i < 512; i += NT) { b0s[i] = g_b0[i]; b1s[i] = g_b1[i]; }
    for (int i = tid; i < 12800; i += NT) a1s[i] = g_A1t[i];
    if (tid < 128) {
        int r = tid >> 4, k = tid & 15;
        embr[r * 16 + k] = turb_emb[turb_idx[brow + r] * 16 + k];
    }
    if (tid < 128) {
        w1ys[tid] = g_W1T[151 * 128 + tid];
        w3s[tid]  = W3[tid];
        bm2s[tid] = b2m[tid];
    }
    if (tid < 100) { cys[tid] = g_cy[tid]; ces[tid] = g_ce[tid]; }
    if (tid == 0) {
        #pragma unroll
        for (int b = 0; b < 4; b++)
            asm volatile("mbarrier.init.shared.b64 [%0], 1;" :: "r"(mbb + b * 8) : "memory");
    }
    __syncthreads();
    if (tid < 128) {
        int k = tid >> 3, r = tid & 7;
        float v = embr[r * 16 + k];
        embT[k * 8 + r] = v;
        xfix[(8 + k) * 8 + r] = v;   // constant emb rows
    }
    const int xk = tid & 7, xr = tid >> 3;
    if (tid < 64) xfix[xk * 8 + xr] = __ldg(&x_hist[((brow + xr) * 96 + 0) * 8 + xk]);
    __syncthreads();

    const int u   = tid >> 1;        // unit 0..127
    const int g0  = u << 2;          // interleaved cols (i,f,g,o) of unit u
    const int r0g = (tid & 1) << 2;  // rows r0g..r0g+3

    const float4 b0v = *reinterpret_cast<const float4*>(b0s + g0);
    const float4 b1v = *reinterpret_cast<const float4*>(b1s + g0);

    float c0r[4] = {0.f, 0.f, 0.f, 0.f};
    float c1r[4] = {0.f, 0.f, 0.f, 0.f};

    float* h0cur = h0A; float* h0nxt = h0B;
    float* h1cur = h1A; float* h1nxt = h1B;
    int gci = 0;   // global chunk counter: buffer = gci&3, parity = (gci>>2)&1

    float xnext = 0.f;
    if (tid < 64) xnext = __ldg(&x_hist[((brow + xr) * 96 + 1) * 8 + xk]);

    // prime pipeline: chunks 0,1,2 -> buffers 0,1,2
    if (tid == 0) {
        bulk_stage(stg_u32,               g_W0ext,           KCBYTES, mbb);
        bulk_stage(stg_u32 + KCBYTES,     g_W0ext + KCF,     KCBYTES, mbb + 8);
        bulk_stage(stg_u32 + 2 * KCBYTES, g_W0ext + 2 * KCF, KCBYTES, mbb + 16);
    }

    // =================== LSTM encoder: 96 steps x 26 chunks ===================
    for (int t = 0; t < 96; t++) {
        ull a00 = 0, a01 = 0, a10 = 0, a11 = 0, a20 = 0, a21 = 0, a30 = 0, a31 = 0;

        #pragma unroll 1
        for (int cc = 0; cc < 26; cc++) {
            const int pb = gci & 3;
            mbar_wait(mbb + pb * 8, (gci >> 2) & 1);
            __syncthreads();   // chunk visible AND all threads done with buffer (pb+3)&3

            // issue chunk cc+3 (wraps to next step; weights repeat each step)
            if (tid == 0 && !(t == 95 && cc >= 23)) {
                int scc = cc + 3; if (scc >= 26) scc -= 26;
                const float* src = (scc < 10) ? (g_W0ext + scc * KCF)
                                              : (g_W1cat + (scc - 10) * KCF);
                int nb = (gci + 3) & 3;
                bulk_stage(stg_u32 + (unsigned)nb * KCBYTES, src, KCBYTES, mbb + nb * 8);
            }
            gci++;

            const float* buf = stg + pb * KCF;
            const float* xb;
            if (cc < 2)       xb = xfix  + cc * 128;
            else if (cc < 10) xb = h0cur + (cc - 2) * 128;
            else if (cc < 18) xb = h0nxt + (cc - 10) * 128;
            else              xb = h1cur + (cc - 18) * 128;

            #pragma unroll
            for (int kk = 0; kk < KC; kk++) {
                const ulonglong2 w = *reinterpret_cast<const ulonglong2*>(buf + (kk << 9) + g0);
                const float4 x = *reinterpret_cast<const float4*>(xb + (kk << 3) + r0g);
                ull d0 = dup2(x.x), d1 = dup2(x.y), d2 = dup2(x.z), d3 = dup2(x.w);
                ffma2(a00, w.x, d0); ffma2(a01, w.y, d0);
                ffma2(a10, w.x, d1); ffma2(a11, w.y, d1);
                ffma2(a20, w.x, d2); ffma2(a21, w.y, d2);
                ffma2(a30, w.x, d3); ffma2(a31, w.y, d3);
            }

            if (cc == 9) {
                // combine layer 0 in registers -> h0nxt
                float h[4];
                {
                    float2 pif, pgo;
                    pif = unpack2(a00); pgo = unpack2(a01);
                    { float gi = pif.x + b0v.x, gf = pif.y + b0v.y;
                      float gg = pgo.x + b0v.z, go = pgo.y + b0v.w;
                      float cv = sigf(gf) * c0r[0] + sigf(gi) * tanhf_fast(gg);
                      c0r[0] = cv; h[0] = sigf(go) * tanhf_fast(cv); }
                    pif = unpack2(a10); pgo = unpack2(a11);
                    { float gi = pif.x + b0v.x, gf = pif.y + b0v.y;
                      float gg = pgo.x + b0v.z, go = pgo.y + b0v.w;
                      float cv = sigf(gf) * c0r[1] + sigf(gi) * tanhf_fast(gg);
                      c0r[1] = cv; h[1] = sigf(go) * tanhf_fast(cv); }
                    pif = unpack2(a20); pgo = unpack2(a21);
                    { float gi = pif.x + b0v.x, gf = pif.y + b0v.y;
                      float gg = pgo.x + b0v.z, go = pgo.y + b0v.w;
                      float cv = sigf(gf) * c0r[2] + sigf(gi) * tanhf_fast(gg);
                      c0r[2] = cv; h[2] = sigf(go) * tanhf_fast(cv); }
                    pif = unpack2(a30); pgo = unpack2(a31);
                    { float gi = pif.x + b0v.x, gf = pif.y + b0v.y;
                      float gg = pgo.x + b0v.z, go = pgo.y + b0v.w;
                      float cv = sigf(gf) * c0r[3] + sigf(gi) * tanhf_fast(gg);
                      c0r[3] = cv; h[3] = sigf(go) * tanhf_fast(cv); }
                }
                *reinterpret_cast<float4*>(&h0nxt[u * 8 + r0g]) = make_float4(h[0], h[1], h[2], h[3]);
                a00 = a01 = a10 = a11 = a20 = a21 = a30 = a31 = 0ULL;
                if (tid < 64) {
                    if (t < 95) xfix[xk * 8 + xr] = xnext;
                    if (t + 2 < 96) xnext = __ldg(&x_hist[((brow + xr) * 96 + (t + 2)) * 8 + xk]);
                }
            } else if (cc == 25) {
                // combine layer 1 in registers -> h1nxt
                float h[4];
                {
                    float2 pif, pgo;
                    pif = unpack2(a00); pgo = unpack2(a01);
                    { float gi = pif.x + b1v.x, gf = pif.y + b1v.y;
                      float gg = pgo.x + b1v.z, go = pgo.y + b1v.w;
                      float cv = sigf(gf) * c1r[0] + sigf(gi) * tanhf_fast(gg);
                      c1r[0] = cv; h[0] = sigf(go) * tanhf_fast(cv); }
                    pif = unpack2(a10); pgo = unpack2(a11);
                    { float gi = pif.x + b1v.x, gf = pif.y + b1v.y;
                      float gg = pgo.x + b1v.z, go = pgo.y + b1v.w;
                      float cv = sigf(gf) * c1r[1] + sigf(gi) * tanhf_fast(gg);
                      c1r[1] = cv; h[1] = sigf(go) * tanhf_fast(cv); }
                    pif = unpack2(a20); pgo = unpack2(a21);
                    { float gi = pif.x + b1v.x, gf = pif.y + b1v.y;
                      float gg = pgo.x + b1v.z, go = pgo.y + b1v.w;
                      float cv = sigf(gf) * c1r[2] + sigf(gi) * tanhf_fast(gg);
                      c1r[2] = cv; h[2] = sigf(go) * tanhf_fast(cv); }
                    pif = unpack2(a30); pgo = unpack2(a31);
                    { float gi = pif.x + b1v.x, gf = pif.y + b1v.y;
                      float gg = pgo.x + b1v.z, go = pgo.y + b1v.w;
                      float cv = sigf(gf) * c1r[3] + sigf(gi) * tanhf_fast(gg);
                      c1r[3] = cv; h[3] = sigf(go) * tanhf_fast(cv); }
                }
                *reinterpret_cast<float4*>(&h1nxt[u * 8 + r0g]) = make_float4(h[0], h[1], h[2], h[3]);
            }
        }

        { float* tmp = h0cur; h0cur = h0nxt; h0nxt = tmp; }
        { float* tmp = h1cur; h1cur = h1nxt; h1nxt = tmp; }
    }
    __syncthreads();
    const float* encf = h1cur;   // final enc_out [128 u][8 r]

    // =================== AR + diffusion (R12-proven, two halves) ===================
    const int half = tid >> 7;
    const int local = tid & 127;
    const int uu = tid & 127;
    const int r0d = half * 4;
    const float b3v = __ldg(&b3p[0]);

    float w2r[128];
    #pragma unroll
    for (int uw = 0; uw < 128; uw++) w2r[uw] = __ldg(&g_W2s[(uw << 7) + uu]);

    const float w1yv = w1ys[uu];
    const float w3v  = w3s[uu];
    const float bm2v = bm2s[uu];
    const ull bm2p = pack2(bm2v, bm2v);

    float ypa[4];
    #pragma unroll
    for (int j = 0; j < 4; j++) ypa[j] = __ldg(&y0[brow + r0d + j]);

    const int wih = (tid >> 5) & 3;
    const int lane = tid & 31;

    for (int p = 0; p < 8; p++) {
        if (local < 24) {
            int k = local >> 2, rl = local & 3;
            xfT[half * 24 + k * 4 + rl] = __ldg(&x_future[(brow + r0d + rl) * 48 + p * 6 + k]);
        }
        if (local < 16) {
            int j = local & 7;
            float f = __expf(-logf(10000.0f) * (float)j / 8.0f);
            float a = (float)p * f;
            hes[half * 16 + local] = (local < 8) ? cosf(a) : sinf(a);
        }
        float yra[4];
        #pragma unroll
        for (int j = 0; j < 4; j++) yra[j] = __ldg(&init_noise[p * 1024 + brow + r0d + j]);
        barh(half);

        float4 base = make_float4(0.f, 0.f, 0.f, 0.f);
        {
            #pragma unroll 8
            for (int k = 0; k < 128; k++) {
                float w = __ldg(&g_W1T[(k << 7) + uu]);
                const float4 h = *reinterpret_cast<const float4*>(&encf[k * 8 + r0d]);
                base.x += w * h.x; base.y += w * h.y; base.z += w * h.z; base.w += w * h.w;
            }
            #pragma unroll
            for (int k = 0; k < 6; k++) {
                float w = __ldg(&g_W1T[((128 + k) << 7) + uu]);
                const float4 x = *reinterpret_cast<const float4*>(&xfT[half * 24 + k * 4]);
                base.x += w * x.x; base.y += w * x.y; base.z += w * x.z; base.w += w * x.w;
            }
            #pragma unroll
            for (int k = 0; k < 16; k++) {
                float w = __ldg(&g_W1T[((134 + k) << 7) + uu]);
                const float* ep = &embT[k * 8 + r0d];
                base.x += w * ep[0]; base.y += w * ep[1]; base.z += w * ep[2]; base.w += w * ep[3];
            }
            {
                float w = __ldg(&g_W1T[(150 << 7) + uu]);
                base.x += w * ypa[0]; base.y += w * ypa[1]; base.z += w * ypa[2]; base.w += w * ypa[3];
            }
            float hsum = 0.f;
            #pragma unroll
            for (int k = 0; k < 16; k++) hsum += __ldg(&g_W1T[((168 + k) << 7) + uu]) * hes[half * 16 + k];
            float bb = __ldg(&b1m[uu]) + hsum;
            base.x += bb; base.y += bb; base.z += bb; base.w += bb;
        }

        for (int tt = 99; tt >= 0; tt--) {
            {
                float av = a1s[tt * 128 + uu];
                float4 m;
                m.x = fmaxf(base.x + yra[0] * w1yv + av, 0.f);
                m.y = fmaxf(base.y + yra[1] * w1yv + av, 0.f);
                m.z = fmaxf(base.z + yra[2] * w1yv + av, 0.f);
                m.w = fmaxf(base.w + yra[3] * w1yv + av, 0.f);
                *reinterpret_cast<float4*>(&mh1[(uu << 3) + r0d]) = m;
            }
            barh(half);

            {
                ull acc01 = bm2p;
                ull acc23 = bm2p;
                #pragma unroll
                for (int uw = 0; uw < 128; uw++) {
                    const ulonglong2 h = *reinterpret_cast<const ulonglong2*>(&mh1[(uw << 3) + r0d]);
                    ull dw = dup2(w2r[uw]);
                    ffma2(acc01, dw, h.x);
                    ffma2(acc23, dw, h.y);
                }
                float2 a01 = unpack2(acc01);
                float2 a23 = unpack2(acc23);
                float e0 = fmaxf(a01.x, 0.f) * w3v;
                float e1 = fmaxf(a01.y, 0.f) * w3v;
                float e2 = fmaxf(a23.x, 0.f) * w3v;
                float e3 = fmaxf(a23.y, 0.f) * w3v;
                #pragma unroll
                for (int off = 16; off > 0; off >>= 1) {
                    e0 += __shfl_down_sync(0xffffffffu, e0, off);
                    e1 += __shfl_down_sync(0xffffffffu, e1, off);
                    e2 += __shfl_down_sync(0xffffffffu, e2, off);
                    e3 += __shfl_down_sync(0xffffffffu, e3, off);
                }
                if (lane == 0)
                    *reinterpret_cast<float4*>(&red[half * 16 + wih * 4]) = make_float4(e0, e1, e2, e3);
            }
            barh(half);

            {
                const float4 q0 = *reinterpret_cast<const float4*>(&red[half * 16 + 0]);
                const float4 q1 = *reinterpret_cast<const float4*>(&red[half * 16 + 4]);
                const float4 q2 = *reinterpret_cast<const float4*>(&red[half * 16 + 8]);
                const float4 q3 = *reinterpret_cast<const float4*>(&red[half * 16 + 12]);
                float cy = cys[tt], ce = ces[tt];
                yra[0] = cy * yra[0] - ce * (b3v + q0.x + q1.x + q2.x + q3.x);
                yra[1] = cy * yra[1] - ce * (b3v + q0.y + q1.y + q2.y + q3.y);
                yra[2] = cy * yra[2] - ce * (b3v + q0.z + q1.z + q2.z + q3.z);
                yra[3] = cy * yra[3] - ce * (b3v + q0.w + q1.w + q2.w + q3.w);
            }
        }

        if (local < 4) {
            float v = (local == 0) ? yra[0] : (local == 1) ? yra[1] : (local == 2) ? yra[2] : yra[3];
            out[(brow + r0d + local) * 8 + p] = v;
        }
        #pragma unroll
        for (int j = 0; j < 4; j++) ypa[j] = yra[j];
    }
}

// ---------------- launch ----------------
extern "C" void kernel_launch(void* const* d_in, const int* in_sizes, int n_in,
                              void* d_out, int out_size) {
    const float* x_hist     = (const float*)d_in[0];
    const float* x_future   = (const float*)d_in[1];
    const float* y0         = (const float*)d_in[2];
    const int*   turb_idx   = (const int*)d_in[3];
    const float* init_noise = (const float*)d_in[5];
    const float* turb_emb   = (const float*)d_in[6];
    const float* W_ih0      = (const float*)d_in[7];
    const float* W_hh0      = (const float*)d_in[8];
    const float* b_ih0      = (const float*)d_in[9];
    const float* b_hh0      = (const float*)d_in[10];
    const float* W_ih1      = (const float*)d_in[11];
    const float* W_hh1      = (const float*)d_in[12];
    const float* b_ih1      = (const float*)d_in[13];
    const float* b_hh1      = (const float*)d_in[14];
    const float* W1         = (const float*)d_in[15];
    const float* b1m        = (const float*)d_in[16];
    const float* W2         = (const float*)d_in[17];
    const float* b2m        = (const float*)d_in[18];
    const float* W3         = (const float*)d_in[19];
    const float* b3         = (const float*)d_in[20];
    float* out = (float*)d_out;

    prologue_kernel<<<128, 256>>>(W_ih0, W_hh0, b_ih0, b_hh0,
                                  W_ih1, W_hh1, b_ih1, b_hh1, W1, W2);

    cudaFuncSetAttribute(fused_kernel, cudaFuncAttributeMaxDynamicSharedMemorySize, SMEM_BYTES);
    fused_kernel<<<NBLK, NT, SMEM_BYTES>>>(x_hist, x_future, y0, turb_idx, init_noise,
                                           turb_emb, b1m, b2m, W3, b3, out);
}